// round 7
// baseline (speedup 1.0000x reference)
#include <cuda_runtime.h>

#define NB     8
#define S_ENC  256
#define S_DEC  128
#define DIM    512     // D_ENC = D_DEC = UNITS = 512

// Scratch for projected encodings/decodings (no cudaMalloc allowed)
__device__ float g_denc[NB * S_ENC * DIM];   // [B, S_ENC, U]
__device__ float g_ddec[NB * S_DEC * DIM];   // [B, S_DEC, U]

// ---------------------------------------------------------------------------
// Merged GEMM: z=0 -> d_enc = enc @ W_enc + b_enc  (M=2048)
//              z=1 -> d_dec = dec @ W_dec + b_dec  (M=1024)
// 64x64 tile, BK=16, 256 threads, 4x4/thread, register-prefetched loads.
// ---------------------------------------------------------------------------
#define GBM 64
#define GBN 64
#define GBK 16

__global__ __launch_bounds__(256) void gemm_bias_kernel(
    const float* __restrict__ Xe, const float* __restrict__ We,
    const float* __restrict__ be, float* __restrict__ Ce,
    const float* __restrict__ Xd, const float* __restrict__ Wd,
    const float* __restrict__ bd, float* __restrict__ Cd)
{
    const int z = blockIdx.z;
    if (z == 1 && blockIdx.y >= (NB * S_DEC) / GBM) return;

    const float* __restrict__ X    = z ? Xd : Xe;
    const float* __restrict__ W    = z ? Wd : We;
    const float* __restrict__ bias = z ? bd : be;
    float* __restrict__ C          = z ? Cd : Ce;

    __shared__ float As[GBK][GBM];
    __shared__ float Bs[GBK][GBN];

    const int tid = threadIdx.x;
    const int tx = tid & 15;
    const int ty = tid >> 4;
    const int row0 = blockIdx.y * GBM;
    const int col0 = blockIdx.x * GBN;

    const int arow = tid >> 2;
    const int acol = (tid & 3) * 4;
    const int brow = tid >> 4;
    const int bcol = (tid & 15) * 4;

    float acc[4][4] = {};

    float4 ra = *(const float4*)&X[(row0 + arow) * DIM + acol];
    float4 rb = *(const float4*)&W[brow * DIM + col0 + bcol];

    for (int k0 = 0; k0 < DIM; k0 += GBK) {
        As[acol + 0][arow] = ra.x;
        As[acol + 1][arow] = ra.y;
        As[acol + 2][arow] = ra.z;
        As[acol + 3][arow] = ra.w;
        *(float4*)&Bs[brow][bcol] = rb;
        __syncthreads();

        if (k0 + GBK < DIM) {
            ra = *(const float4*)&X[(row0 + arow) * DIM + k0 + GBK + acol];
            rb = *(const float4*)&W[(k0 + GBK + brow) * DIM + col0 + bcol];
        }

        #pragma unroll
        for (int k = 0; k < GBK; k++) {
            float4 av = *(const float4*)&As[k][ty * 4];
            float4 bv = *(const float4*)&Bs[k][tx * 4];
            float ar[4] = {av.x, av.y, av.z, av.w};
            float br[4] = {bv.x, bv.y, bv.z, bv.w};
            #pragma unroll
            for (int i = 0; i < 4; i++)
                #pragma unroll
                for (int j = 0; j < 4; j++)
                    acc[i][j] = fmaf(ar[i], br[j], acc[i][j]);
        }
        __syncthreads();
    }

    #pragma unroll
    for (int i = 0; i < 4; i++) {
        const int r = row0 + ty * 4 + i;
        #pragma unroll
        for (int j = 0; j < 4; j++) {
            const int c = col0 + tx * 4 + j;
            C[r * DIM + c] = acc[i][j] + bias[c];
        }
    }
}

// ---------------------------------------------------------------------------
// Attention kernel.
// Block = (batch b, tile of QT=8 q's), 1024 threads = 32 warps.
// Warp w -> (q = w>>2, u-quarter = w&3): ddr[4]/wsr[4] in registers.
// Each lane accumulates partial scores for EB=16 encoder rows (acc[16]);
// reduced with a multi-value butterfly (~1 shfl/e). Four warps' quarter-sums
// combined via SMEM. d_enc streamed with cp.async double-buffering (no
// prefetch registers -> fits the 64-reg budget of 1024-thread blocks).
// ---------------------------------------------------------------------------
#define QT   8
#define EB   16                  // encoder rows per chunk
#define NCH  (S_ENC / EB)        // 16
#define ATH  1024
#define CHV  (EB * DIM / 4)      // 2048 float4 per chunk
#define PFT  (CHV / ATH)         // 2 float4 per thread

__device__ __forceinline__ float tanh_approx(float x) {
    float y;
    asm("tanh.approx.f32 %0, %1;" : "=f"(y) : "f"(x));
    return y;
}

__global__ __launch_bounds__(ATH, 1) void attn_kernel(
    const float* __restrict__ enc,      // [B, S_ENC, DIM] raw encodings
    const float* __restrict__ wscore,   // [DIM]
    const float* __restrict__ bscore,   // [1]
    float* __restrict__ out)            // [B, S_DEC, DIM]
{
    extern __shared__ float smem[];
    float* s_de   = smem;                         // 2*EB*DIM   (16384 f)
    float* s_part = s_de + 2 * EB * DIM;          // 32*S_ENC   (8192 f)
    float* s_sc   = s_part + 32 * S_ENC;          // QT*S_ENC   (2048 f)
    float* s_t    = s_sc + QT * S_ENC;            // S_ENC*QT   (2048 f)

    const int b    = blockIdx.y;
    const int q0   = blockIdx.x * QT;
    const int tid  = threadIdx.x;
    const int lane = tid & 31;
    const int w    = tid >> 5;
    const int q    = w >> 2;            // local q in [0,8)
    const int quad = w & 3;             // u-quarter
    const int u0   = quad * 128 + lane;

    // ---- loop-invariant registers -----------------------------------------
    float ddr[4], wsr[4];
    {
        const float* ddp = g_ddec + (b * S_DEC + q0 + q) * DIM;
        #pragma unroll
        for (int i = 0; i < 4; i++) {
            ddr[i] = ddp[u0 + 32 * i];
            wsr[i] = wscore[u0 + 32 * i];
        }
    }

    const float4* gsrc = (const float4*)(g_denc + b * S_ENC * DIM);
    const unsigned sde_base = (unsigned)__cvta_generic_to_shared(s_de);

    // cp.async chunk prefetch: thread copies PFT float4 -> buf
    #define ISSUE_CHUNK(ch, buf)                                               \
        do {                                                                   \
            _Pragma("unroll")                                                  \
            for (int j = 0; j < PFT; j++) {                                    \
                const int idx = j * ATH + tid;                                 \
                const unsigned dst = sde_base + ((buf) * CHV + idx) * 16u;     \
                const float4* srcp = gsrc + (ch) * CHV + idx;                  \
                asm volatile("cp.async.ca.shared.global [%0], [%1], 16;\n"     \
                             :: "r"(dst), "l"(srcp));                          \
            }                                                                  \
            asm volatile("cp.async.commit_group;\n");                          \
        } while (0)

    ISSUE_CHUNK(0, 0);
    ISSUE_CHUNK(1, 1);
    asm volatile("cp.async.wait_group 1;\n");
    __syncthreads();

    // ---- score chunks ------------------------------------------------------
    for (int ch = 0; ch < NCH; ch++) {
        const float* de = s_de + (ch & 1) * EB * DIM + u0;

        float acc[EB];
        #pragma unroll
        for (int e = 0; e < EB; e++) {
            float s = 0.f;
            #pragma unroll
            for (int i = 0; i < 4; i++) {
                const float x = ddr[i] + de[e * DIM + 32 * i];
                s = fmaf(tanh_approx(x), wsr[i], s);
            }
            acc[e] = s;
        }

        // multi-value butterfly: fold 16 values over stages s=16..2, then s=1
        #pragma unroll
        for (int s = 16, n = 8; s >= 2; s >>= 1, n >>= 1) {
            const bool hi = (lane & s) != 0;
            #pragma unroll
            for (int j = 0; j < n; j++) {
                const float send = hi ? acc[j] : acc[j + n];
                const float keep = hi ? acc[j + n] : acc[j];
                acc[j] = keep + __shfl_xor_sync(0xFFFFFFFFu, send, s);
            }
        }
        acc[0] += __shfl_xor_sync(0xFFFFFFFFu, acc[0], 1);
        // lane holds sum for e = (lane>>1)&15; even lanes write
        if ((lane & 1) == 0)
            s_part[w * S_ENC + ch * EB + ((lane >> 1) & 15)] = acc[0];

        if (ch + 1 < NCH) {
            __syncthreads();                       // done reading buf[ch&1]
            if (ch + 2 < NCH) {
                ISSUE_CHUNK(ch + 2, (ch & 1));
                asm volatile("cp.async.wait_group 1;\n");   // chunk ch+1 ready
            } else {
                asm volatile("cp.async.wait_group 0;\n");
            }
            __syncthreads();                       // new buffer visible
        }
    }
    __syncthreads();   // all s_part written

    // ---- combine quarter-sums + bias --------------------------------------
    const float bsc = bscore[0];
    for (int idx = tid; idx < QT * S_ENC; idx += ATH) {
        const int qq = idx >> 8, e = idx & (S_ENC - 1);
        s_sc[qq * S_ENC + e] =
            s_part[(4 * qq + 0) * S_ENC + e] + s_part[(4 * qq + 1) * S_ENC + e] +
            s_part[(4 * qq + 2) * S_ENC + e] + s_part[(4 * qq + 3) * S_ENC + e] + bsc;
    }
    __syncthreads();

    // ---- softmax (warps 0-7 handle q=w); write transposed [e][q] ----------
    if (w < QT) {
        float v[S_ENC / 32];
        float m = -1e30f;
        #pragma unroll
        for (int i = 0; i < S_ENC / 32; i++) {
            v[i] = s_sc[w * S_ENC + lane + 32 * i];
            m = fmaxf(m, v[i]);
        }
        #pragma unroll
        for (int off = 16; off; off >>= 1)
            m = fmaxf(m, __shfl_xor_sync(0xFFFFFFFFu, m, off));
        float sum = 0.f;
        #pragma unroll
        for (int i = 0; i < S_ENC / 32; i++) {
            v[i] = __expf(v[i] - m);
            sum += v[i];
        }
        #pragma unroll
        for (int off = 16; off; off >>= 1)
            sum += __shfl_xor_sync(0xFFFFFFFFu, sum, off);
        const float inv = 1.f / sum;
        #pragma unroll
        for (int i = 0; i < S_ENC / 32; i++)
            s_t[(lane + 32 * i) * QT + w] = v[i] * inv;
    }
    __syncthreads();

    // ---- context: warp w owns dims [w*16, w*16+16); half-warps split e ----
    const int dl = lane & 15;
    const int eh = lane >> 4;           // 0/1 -> e-half
    const int d0 = w * 16 + dl;
    float c[QT] = {};
    const float* ep = enc + b * S_ENC * DIM;

    const int e_beg = eh * 128;
    #pragma unroll 4
    for (int e = e_beg; e < e_beg + 128; e++) {
        const float ev = ep[e * DIM + d0];
        const float4 w0 = *(const float4*)&s_t[e * QT];       // broadcast
        const float4 w1 = *(const float4*)&s_t[e * QT + 4];
        c[0] = fmaf(w0.x, ev, c[0]);
        c[1] = fmaf(w0.y, ev, c[1]);
        c[2] = fmaf(w0.z, ev, c[2]);
        c[3] = fmaf(w0.w, ev, c[3]);
        c[4] = fmaf(w1.x, ev, c[4]);
        c[5] = fmaf(w1.y, ev, c[5]);
        c[6] = fmaf(w1.z, ev, c[6]);
        c[7] = fmaf(w1.w, ev, c[7]);
    }
    #pragma unroll
    for (int qq = 0; qq < QT; qq++)
        c[qq] += __shfl_xor_sync(0xFFFFFFFFu, c[qq], 16);

    if (lane < 16) {
        #pragma unroll
        for (int qq = 0; qq < QT; qq++)
            out[(b * S_DEC + q0 + qq) * DIM + d0] = c[qq];
    }
}

#define ATTN_SMEM ((2 * EB * DIM + 32 * S_ENC + 2 * QT * S_ENC) * (int)sizeof(float))

// ---------------------------------------------------------------------------
extern "C" void kernel_launch(void* const* d_in, const int* in_sizes, int n_in,
                              void* d_out, int out_size)
{
    const float* encodings = (const float*)d_in[0];   // [8,256,512]
    const float* decodings = (const float*)d_in[1];   // [8,128,512]
    const float* W_enc     = (const float*)d_in[2];   // [512,512]
    const float* W_dec     = (const float*)d_in[3];   // [512,512]
    const float* W_score   = (const float*)d_in[4];   // [512,1]
    const float* bias_enc  = (const float*)d_in[5];   // [512]
    const float* bias_dec  = (const float*)d_in[6];   // [512]
    const float* bias_sc   = (const float*)d_in[7];   // [1]
    float* out = (float*)d_out;                       // [8,128,512]

    void* p_denc = nullptr;
    void* p_ddec = nullptr;
    cudaGetSymbolAddress(&p_denc, g_denc);
    cudaGetSymbolAddress(&p_ddec, g_ddec);

    cudaFuncSetAttribute(attn_kernel,
                         cudaFuncAttributeMaxDynamicSharedMemorySize, ATTN_SMEM);

    // both projections in one launch (z dimension selects)
    {
        dim3 grid(DIM / GBN, (NB * S_ENC) / GBM, 2);   // (8, 32, 2)
        gemm_bias_kernel<<<grid, 256>>>(encodings, W_enc, bias_enc, (float*)p_denc,
                                        decodings, W_dec, bias_dec, (float*)p_ddec);
    }

    // scores + softmax + context
    {
        dim3 grid(S_DEC / QT, NB);                     // (16, 8)
        attn_kernel<<<grid, ATH, ATTN_SMEM>>>(encodings, W_score, bias_sc, out);
    }
}

// round 8
// speedup vs baseline: 1.1955x; 1.1955x over previous
#include <cuda_runtime.h>
#include <cstdint>

#define NB     8
#define S_ENC  256
#define S_DEC  128
#define DIM    512     // D_ENC = D_DEC = UNITS = 512

// Scratch for projected encodings/decodings (no cudaMalloc allowed)
__device__ float g_denc[NB * S_ENC * DIM];   // [B, S_ENC, U]
__device__ float g_ddec[NB * S_DEC * DIM];   // [B, S_DEC, U]

// ---------------------------------------------------------------------------
// tf32 tensor-core GEMM (3xTF32 split -> fp32-level accuracy).
//   z=0 : d_enc = enc @ W_enc + b_enc   (M=2048)
//   z=1 : d_dec = dec @ W_dec + b_dec   (M=1024)
// Block: 128 threads = 2x2 warps. Block tile 64x64, warp tile 32x32, Kc=32.
// cp.async double-buffered staging; SMEM strides 36/72 floats chosen so all
// fragment LDS patterns are bank-conflict-free.
// ---------------------------------------------------------------------------
#define TBM 64
#define TBN 64
#define TBK 32
#define ASTR 36              // A smem row stride (floats)
#define BSTR 72              // B smem row stride (floats)
#define NC  (DIM / TBK)      // 16 k-chunks

__device__ __forceinline__ uint32_t f2tf32(float x) {
    uint32_t u;
    asm("cvt.rna.tf32.f32 %0, %1;" : "=r"(u) : "f"(x));
    return u;
}
__device__ __forceinline__ void split_tf32(float x, uint32_t& hi, uint32_t& lo) {
    hi = f2tf32(x);
    lo = f2tf32(x - __uint_as_float(hi));
}
__device__ __forceinline__ void mma_tf32(float c[4], const uint32_t a[4],
                                         const uint32_t b[2]) {
    asm volatile(
        "mma.sync.aligned.m16n8k8.row.col.f32.tf32.tf32.f32 "
        "{%0,%1,%2,%3}, {%4,%5,%6,%7}, {%8,%9}, {%0,%1,%2,%3};"
        : "+f"(c[0]), "+f"(c[1]), "+f"(c[2]), "+f"(c[3])
        : "r"(a[0]), "r"(a[1]), "r"(a[2]), "r"(a[3]), "r"(b[0]), "r"(b[1]));
}

__global__ __launch_bounds__(128) void gemm_tf32_kernel(
    const float* __restrict__ Xe, const float* __restrict__ We,
    const float* __restrict__ be, float* __restrict__ Ce,
    const float* __restrict__ Xd, const float* __restrict__ Wd,
    const float* __restrict__ bd, float* __restrict__ Cd)
{
    const int z = blockIdx.z;
    if (z == 1 && blockIdx.y >= (NB * S_DEC) / TBM) return;

    const float* __restrict__ X    = z ? Xd : Xe;
    const float* __restrict__ W    = z ? Wd : We;
    const float* __restrict__ bias = z ? bd : be;
    float* __restrict__ C          = z ? Cd : Ce;

    __shared__ float As[2][TBM * ASTR];
    __shared__ float Bs[2][TBK * BSTR];
    __shared__ float bsm[TBN];

    const int tid  = threadIdx.x;
    const int lane = tid & 31;
    const int warp = tid >> 5;
    const int wm   = warp >> 1;          // 0..1
    const int wn   = warp & 1;           // 0..1
    const int row0 = blockIdx.y * TBM;
    const int col0 = blockIdx.x * TBN;

    if (tid < TBN) bsm[tid] = bias[col0 + tid];

    // cp.async staging: A = 512 float4, B = 512 float4; 4+4 per thread
    const int ar = (tid >> 1);                 // shared across j via idx math below
    #define ISSUE_GEMM_CHUNK(ch, st)                                           \
        do {                                                                   \
            const int k0 = (ch) * TBK;                                         \
            _Pragma("unroll")                                                  \
            for (int j = 0; j < 4; j++) {                                      \
                const int idx = j * 128 + tid;                                 \
                const int r = idx >> 3, c = (idx & 7) * 4;                     \
                const unsigned dst = (unsigned)__cvta_generic_to_shared(       \
                    &As[st][r * ASTR + c]);                                    \
                const float* src = &X[(row0 + r) * DIM + k0 + c];              \
                asm volatile("cp.async.cg.shared.global [%0], [%1], 16;\n"     \
                             :: "r"(dst), "l"(src));                           \
            }                                                                  \
            _Pragma("unroll")                                                  \
            for (int j = 0; j < 4; j++) {                                      \
                const int idx = j * 128 + tid;                                 \
                const int r = idx >> 4, c = (idx & 15) * 4;                    \
                const unsigned dst = (unsigned)__cvta_generic_to_shared(       \
                    &Bs[st][r * BSTR + c]);                                    \
                const float* src = &W[(k0 + r) * DIM + col0 + c];              \
                asm volatile("cp.async.cg.shared.global [%0], [%1], 16;\n"     \
                             :: "r"(dst), "l"(src));                           \
            }                                                                  \
            asm volatile("cp.async.commit_group;\n");                          \
        } while (0)

    (void)ar;
    float acc[2][4][4] = {};   // [mt][nt][reg]

    ISSUE_GEMM_CHUNK(0, 0);
    ISSUE_GEMM_CHUNK(1, 1);
    asm volatile("cp.async.wait_group 1;\n");
    __syncthreads();

    for (int ch = 0; ch < NC; ch++) {
        const int st = ch & 1;
        const float* A = As[st];
        const float* B = Bs[st];

        #pragma unroll
        for (int ks = 0; ks < TBK / 8; ks++) {
            const int k = ks * 8;
            // ---- A fragments (2 m-tiles), split hi/lo ----
            uint32_t ahi[2][4], alo[2][4];
            #pragma unroll
            for (int mt = 0; mt < 2; mt++) {
                const int m = wm * 32 + mt * 16;
                const int r = m + (lane >> 2);
                const int c = k + (lane & 3);
                split_tf32(A[r * ASTR + c],           ahi[mt][0], alo[mt][0]);
                split_tf32(A[(r + 8) * ASTR + c],     ahi[mt][1], alo[mt][1]);
                split_tf32(A[r * ASTR + c + 4],       ahi[mt][2], alo[mt][2]);
                split_tf32(A[(r + 8) * ASTR + c + 4], ahi[mt][3], alo[mt][3]);
            }
            // ---- B fragments (4 n-tiles), split hi/lo ----
            uint32_t bhi[4][2], blo[4][2];
            #pragma unroll
            for (int nt = 0; nt < 4; nt++) {
                const int n = wn * 32 + nt * 8 + (lane >> 2);
                const int r = k + (lane & 3);
                split_tf32(B[r * BSTR + n],       bhi[nt][0], blo[nt][0]);
                split_tf32(B[(r + 4) * BSTR + n], bhi[nt][1], blo[nt][1]);
            }
            // ---- 3 passes ----
            #pragma unroll
            for (int mt = 0; mt < 2; mt++)
                #pragma unroll
                for (int nt = 0; nt < 4; nt++) {
                    mma_tf32(acc[mt][nt], ahi[mt], bhi[nt]);
                    mma_tf32(acc[mt][nt], ahi[mt], blo[nt]);
                    mma_tf32(acc[mt][nt], alo[mt], bhi[nt]);
                }
        }

        __syncthreads();                       // done reading stage st
        if (ch + 2 < NC) {
            ISSUE_GEMM_CHUNK(ch + 2, st);
            asm volatile("cp.async.wait_group 1;\n");
            __syncthreads();
        } else if (ch + 1 < NC) {
            asm volatile("cp.async.wait_group 0;\n");
            __syncthreads();
        }
    }

    // ---- epilogue: bias + store (float2 per frag row) ---------------------
    #pragma unroll
    for (int mt = 0; mt < 2; mt++) {
        const int r = row0 + wm * 32 + mt * 16 + (lane >> 2);
        #pragma unroll
        for (int nt = 0; nt < 4; nt++) {
            const int cl = wn * 32 + nt * 8 + (lane & 3) * 2;
            const float b0 = bsm[cl], b1 = bsm[cl + 1];
            float2 v0 = {acc[mt][nt][0] + b0, acc[mt][nt][1] + b1};
            float2 v1 = {acc[mt][nt][2] + b0, acc[mt][nt][3] + b1};
            *(float2*)&C[r * DIM + col0 + cl]       = v0;
            *(float2*)&C[(r + 8) * DIM + col0 + cl] = v1;
        }
    }
}

// ---------------------------------------------------------------------------
// Attention kernel (unchanged from R6 — passing, 69 µs).
// Block = (batch b, tile of QT=8 q's), 1024 threads = 32 warps.
// ---------------------------------------------------------------------------
#define QT   8
#define EB   16                  // encoder rows per chunk
#define NCH  (S_ENC / EB)        // 16
#define ATH  1024
#define CHV  (EB * DIM / 4)      // 2048 float4 per chunk
#define PFT  (CHV / ATH)         // 2 float4 per thread

__device__ __forceinline__ float tanh_approx(float x) {
    float y;
    asm("tanh.approx.f32 %0, %1;" : "=f"(y) : "f"(x));
    return y;
}

__global__ __launch_bounds__(ATH, 1) void attn_kernel(
    const float* __restrict__ enc,      // [B, S_ENC, DIM] raw encodings
    const float* __restrict__ wscore,   // [DIM]
    const float* __restrict__ bscore,   // [1]
    float* __restrict__ out)            // [B, S_DEC, DIM]
{
    extern __shared__ float smem[];
    float* s_de   = smem;                         // 2*EB*DIM   (16384 f)
    float* s_part = s_de + 2 * EB * DIM;          // 32*S_ENC   (8192 f)
    float* s_sc   = s_part + 32 * S_ENC;          // QT*S_ENC   (2048 f)
    float* s_t    = s_sc + QT * S_ENC;            // S_ENC*QT   (2048 f)

    const int b    = blockIdx.y;
    const int q0   = blockIdx.x * QT;
    const int tid  = threadIdx.x;
    const int lane = tid & 31;
    const int w    = tid >> 5;
    const int q    = w >> 2;            // local q in [0,8)
    const int quad = w & 3;             // u-quarter
    const int u0   = quad * 128 + lane;

    // ---- loop-invariant registers -----------------------------------------
    float ddr[4], wsr[4];
    {
        const float* ddp = g_ddec + (b * S_DEC + q0 + q) * DIM;
        #pragma unroll
        for (int i = 0; i < 4; i++) {
            ddr[i] = ddp[u0 + 32 * i];
            wsr[i] = wscore[u0 + 32 * i];
        }
    }

    const float4* gsrc = (const float4*)(g_denc + b * S_ENC * DIM);
    const unsigned sde_base = (unsigned)__cvta_generic_to_shared(s_de);

    #define ISSUE_CHUNK(ch, buf)                                               \
        do {                                                                   \
            _Pragma("unroll")                                                  \
            for (int j = 0; j < PFT; j++) {                                    \
                const int idx = j * ATH + tid;                                 \
                const unsigned dst = sde_base + ((buf) * CHV + idx) * 16u;     \
                const float4* srcp = gsrc + (ch) * CHV + idx;                  \
                asm volatile("cp.async.cg.shared.global [%0], [%1], 16;\n"     \
                             :: "r"(dst), "l"(srcp));                          \
            }                                                                  \
            asm volatile("cp.async.commit_group;\n");                          \
        } while (0)

    ISSUE_CHUNK(0, 0);
    ISSUE_CHUNK(1, 1);
    asm volatile("cp.async.wait_group 1;\n");
    __syncthreads();

    // ---- score chunks ------------------------------------------------------
    for (int ch = 0; ch < NCH; ch++) {
        const float* de = s_de + (ch & 1) * EB * DIM + u0;

        float acc[EB];
        #pragma unroll
        for (int e = 0; e < EB; e++) {
            float s = 0.f;
            #pragma unroll
            for (int i = 0; i < 4; i++) {
                const float x = ddr[i] + de[e * DIM + 32 * i];
                s = fmaf(tanh_approx(x), wsr[i], s);
            }
            acc[e] = s;
        }

        // multi-value butterfly: fold 16 values over stages s=16..2, then s=1
        #pragma unroll
        for (int s = 16, n = 8; s >= 2; s >>= 1, n >>= 1) {
            const bool hi = (lane & s) != 0;
            #pragma unroll
            for (int j = 0; j < n; j++) {
                const float send = hi ? acc[j] : acc[j + n];
                const float keep = hi ? acc[j + n] : acc[j];
                acc[j] = keep + __shfl_xor_sync(0xFFFFFFFFu, send, s);
            }
        }
        acc[0] += __shfl_xor_sync(0xFFFFFFFFu, acc[0], 1);
        if ((lane & 1) == 0)
            s_part[w * S_ENC + ch * EB + ((lane >> 1) & 15)] = acc[0];

        if (ch + 1 < NCH) {
            __syncthreads();                       // done reading buf[ch&1]
            if (ch + 2 < NCH) {
                ISSUE_CHUNK(ch + 2, (ch & 1));
                asm volatile("cp.async.wait_group 1;\n");
            } else {
                asm volatile("cp.async.wait_group 0;\n");
            }
            __syncthreads();                       // new buffer visible
        }
    }
    __syncthreads();   // all s_part written

    // ---- combine quarter-sums + bias --------------------------------------
    const float bsc = bscore[0];
    for (int idx = tid; idx < QT * S_ENC; idx += ATH) {
        const int qq = idx >> 8, e = idx & (S_ENC - 1);
        s_sc[qq * S_ENC + e] =
            s_part[(4 * qq + 0) * S_ENC + e] + s_part[(4 * qq + 1) * S_ENC + e] +
            s_part[(4 * qq + 2) * S_ENC + e] + s_part[(4 * qq + 3) * S_ENC + e] + bsc;
    }
    __syncthreads();

    // ---- softmax (warps 0-7 handle q=w); write transposed [e][q] ----------
    if (w < QT) {
        float v[S_ENC / 32];
        float m = -1e30f;
        #pragma unroll
        for (int i = 0; i < S_ENC / 32; i++) {
            v[i] = s_sc[w * S_ENC + lane + 32 * i];
            m = fmaxf(m, v[i]);
        }
        #pragma unroll
        for (int off = 16; off; off >>= 1)
            m = fmaxf(m, __shfl_xor_sync(0xFFFFFFFFu, m, off));
        float sum = 0.f;
        #pragma unroll
        for (int i = 0; i < S_ENC / 32; i++) {
            v[i] = __expf(v[i] - m);
            sum += v[i];
        }
        #pragma unroll
        for (int off = 16; off; off >>= 1)
            sum += __shfl_xor_sync(0xFFFFFFFFu, sum, off);
        const float inv = 1.f / sum;
        #pragma unroll
        for (int i = 0; i < S_ENC / 32; i++)
            s_t[(lane + 32 * i) * QT + w] = v[i] * inv;
    }
    __syncthreads();

    // ---- context: warp w owns dims [w*16, w*16+16); half-warps split e ----
    const int dl = lane & 15;
    const int eh = lane >> 4;           // 0/1 -> e-half
    const int d0 = w * 16 + dl;
    float c[QT] = {};
    const float* ep = enc + b * S_ENC * DIM;

    const int e_beg = eh * 128;
    #pragma unroll 4
    for (int e = e_beg; e < e_beg + 128; e++) {
        const float ev = ep[e * DIM + d0];
        const float4 w0 = *(const float4*)&s_t[e * QT];       // broadcast
        const float4 w1 = *(const float4*)&s_t[e * QT + 4];
        c[0] = fmaf(w0.x, ev, c[0]);
        c[1] = fmaf(w0.y, ev, c[1]);
        c[2] = fmaf(w0.z, ev, c[2]);
        c[3] = fmaf(w0.w, ev, c[3]);
        c[4] = fmaf(w1.x, ev, c[4]);
        c[5] = fmaf(w1.y, ev, c[5]);
        c[6] = fmaf(w1.z, ev, c[6]);
        c[7] = fmaf(w1.w, ev, c[7]);
    }
    #pragma unroll
    for (int qq = 0; qq < QT; qq++)
        c[qq] += __shfl_xor_sync(0xFFFFFFFFu, c[qq], 16);

    if (lane < 16) {
        #pragma unroll
        for (int qq = 0; qq < QT; qq++)
            out[(b * S_DEC + q0 + qq) * DIM + d0] = c[qq];
    }
}

#define ATTN_SMEM ((2 * EB * DIM + 32 * S_ENC + 2 * QT * S_ENC) * (int)sizeof(float))

// ---------------------------------------------------------------------------
extern "C" void kernel_launch(void* const* d_in, const int* in_sizes, int n_in,
                              void* d_out, int out_size)
{
    const float* encodings = (const float*)d_in[0];   // [8,256,512]
    const float* decodings = (const float*)d_in[1];   // [8,128,512]
    const float* W_enc     = (const float*)d_in[2];   // [512,512]
    const float* W_dec     = (const float*)d_in[3];   // [512,512]
    const float* W_score   = (const float*)d_in[4];   // [512,1]
    const float* bias_enc  = (const float*)d_in[5];   // [512]
    const float* bias_dec  = (const float*)d_in[6];   // [512]
    const float* bias_sc   = (const float*)d_in[7];   // [1]
    float* out = (float*)d_out;                       // [8,128,512]

    void* p_denc = nullptr;
    void* p_ddec = nullptr;
    cudaGetSymbolAddress(&p_denc, g_denc);
    cudaGetSymbolAddress(&p_ddec, g_ddec);

    cudaFuncSetAttribute(attn_kernel,
                         cudaFuncAttributeMaxDynamicSharedMemorySize, ATTN_SMEM);

    // both projections in one tensor-core launch (z selects enc/dec)
    {
        dim3 grid(DIM / TBN, (NB * S_ENC) / TBM, 2);   // (8, 32, 2)
        gemm_tf32_kernel<<<grid, 128>>>(encodings, W_enc, bias_enc, (float*)p_denc,
                                        decodings, W_dec, bias_dec, (float*)p_ddec);
    }

    // scores + softmax + context
    {
        dim3 grid(S_DEC / QT, NB);                     // (16, 8)
        attn_kernel<<<grid, ATH, ATTN_SMEM>>>(encodings, W_score, bias_sc, out);
    }
}

// round 10
// speedup vs baseline: 1.2042x; 1.0073x over previous
#include <cuda_runtime.h>
#include <cuda_fp16.h>
#include <cstdint>

#define NB     8
#define S_ENC  256
#define S_DEC  128
#define DIM    512     // D_ENC = D_DEC = UNITS = 512

// Scratch for projected encodings/decodings (no cudaMalloc allowed)
__device__ float g_denc[NB * S_ENC * DIM];   // [B, S_ENC, U]
__device__ float g_ddec[NB * S_DEC * DIM];   // [B, S_DEC, U]

// ---------------------------------------------------------------------------
// tf32 tensor-core GEMM (3xTF32 split -> fp32-level accuracy).
//   z=0 : d_enc = enc @ W_enc + b_enc   (M=2048)
//   z=1 : d_dec = dec @ W_dec + b_dec   (M=1024)
// Block: 128 threads = 2x2 warps. Block tile 64x64, warp tile 32x32, Kc=32.
// ---------------------------------------------------------------------------
#define TBM 64
#define TBN 64
#define TBK 32
#define ASTR 36              // A smem row stride (floats)
#define BSTR 72              // B smem row stride (floats)
#define NC  (DIM / TBK)      // 16 k-chunks

__device__ __forceinline__ uint32_t f2tf32(float x) {
    uint32_t u;
    asm("cvt.rna.tf32.f32 %0, %1;" : "=r"(u) : "f"(x));
    return u;
}
__device__ __forceinline__ void split_tf32(float x, uint32_t& hi, uint32_t& lo) {
    hi = f2tf32(x);
    lo = f2tf32(x - __uint_as_float(hi));
}
__device__ __forceinline__ void mma_tf32(float c[4], const uint32_t a[4],
                                         const uint32_t b[2]) {
    asm volatile(
        "mma.sync.aligned.m16n8k8.row.col.f32.tf32.tf32.f32 "
        "{%0,%1,%2,%3}, {%4,%5,%6,%7}, {%8,%9}, {%0,%1,%2,%3};"
        : "+f"(c[0]), "+f"(c[1]), "+f"(c[2]), "+f"(c[3])
        : "r"(a[0]), "r"(a[1]), "r"(a[2]), "r"(a[3]), "r"(b[0]), "r"(b[1]));
}

__global__ __launch_bounds__(128) void gemm_tf32_kernel(
    const float* __restrict__ Xe, const float* __restrict__ We,
    const float* __restrict__ be, float* __restrict__ Ce,
    const float* __restrict__ Xd, const float* __restrict__ Wd,
    const float* __restrict__ bd, float* __restrict__ Cd)
{
    const int z = blockIdx.z;
    if (z == 1 && blockIdx.y >= (NB * S_DEC) / TBM) return;

    const float* __restrict__ X    = z ? Xd : Xe;
    const float* __restrict__ W    = z ? Wd : We;
    const float* __restrict__ bias = z ? bd : be;
    float* __restrict__ C          = z ? Cd : Ce;

    __shared__ float As[2][TBM * ASTR];
    __shared__ float Bs[2][TBK * BSTR];
    __shared__ float bsm[TBN];

    const int tid  = threadIdx.x;
    const int lane = tid & 31;
    const int warp = tid >> 5;
    const int wm   = warp >> 1;          // 0..1
    const int wn   = warp & 1;           // 0..1
    const int row0 = blockIdx.y * TBM;
    const int col0 = blockIdx.x * TBN;

    if (tid < TBN) bsm[tid] = bias[col0 + tid];

    #define ISSUE_GEMM_CHUNK(ch, st)                                           \
        do {                                                                   \
            const int k0 = (ch) * TBK;                                         \
            _Pragma("unroll")                                                  \
            for (int j = 0; j < 4; j++) {                                      \
                const int idx = j * 128 + tid;                                 \
                const int r = idx >> 3, c = (idx & 7) * 4;                     \
                const unsigned dst = (unsigned)__cvta_generic_to_shared(       \
                    &As[st][r * ASTR + c]);                                    \
                const float* src = &X[(row0 + r) * DIM + k0 + c];              \
                asm volatile("cp.async.cg.shared.global [%0], [%1], 16;\n"     \
                             :: "r"(dst), "l"(src));                           \
            }                                                                  \
            _Pragma("unroll")                                                  \
            for (int j = 0; j < 4; j++) {                                      \
                const int idx = j * 128 + tid;                                 \
                const int r = idx >> 4, c = (idx & 15) * 4;                    \
                const unsigned dst = (unsigned)__cvta_generic_to_shared(       \
                    &Bs[st][r * BSTR + c]);                                    \
                const float* src = &W[(k0 + r) * DIM + col0 + c];              \
                asm volatile("cp.async.cg.shared.global [%0], [%1], 16;\n"     \
                             :: "r"(dst), "l"(src));                           \
            }                                                                  \
            asm volatile("cp.async.commit_group;\n");                          \
        } while (0)

    float acc[2][4][4] = {};   // [mt][nt][reg]

    ISSUE_GEMM_CHUNK(0, 0);
    ISSUE_GEMM_CHUNK(1, 1);
    asm volatile("cp.async.wait_group 1;\n");
    __syncthreads();

    for (int ch = 0; ch < NC; ch++) {
        const int st = ch & 1;
        const float* A = As[st];
        const float* B = Bs[st];

        #pragma unroll
        for (int ks = 0; ks < TBK / 8; ks++) {
            const int k = ks * 8;
            uint32_t ahi[2][4], alo[2][4];
            #pragma unroll
            for (int mt = 0; mt < 2; mt++) {
                const int m = wm * 32 + mt * 16;
                const int r = m + (lane >> 2);
                const int c = k + (lane & 3);
                split_tf32(A[r * ASTR + c],           ahi[mt][0], alo[mt][0]);
                split_tf32(A[(r + 8) * ASTR + c],     ahi[mt][1], alo[mt][1]);
                split_tf32(A[r * ASTR + c + 4],       ahi[mt][2], alo[mt][2]);
                split_tf32(A[(r + 8) * ASTR + c + 4], ahi[mt][3], alo[mt][3]);
            }
            uint32_t bhi[4][2], blo[4][2];
            #pragma unroll
            for (int nt = 0; nt < 4; nt++) {
                const int n = wn * 32 + nt * 8 + (lane >> 2);
                const int r = k + (lane & 3);
                split_tf32(B[r * BSTR + n],       bhi[nt][0], blo[nt][0]);
                split_tf32(B[(r + 4) * BSTR + n], bhi[nt][1], blo[nt][1]);
            }
            #pragma unroll
            for (int mt = 0; mt < 2; mt++)
                #pragma unroll
                for (int nt = 0; nt < 4; nt++) {
                    mma_tf32(acc[mt][nt], ahi[mt], bhi[nt]);
                    mma_tf32(acc[mt][nt], ahi[mt], blo[nt]);
                    mma_tf32(acc[mt][nt], alo[mt], bhi[nt]);
                }
        }

        __syncthreads();                       // done reading stage st
        if (ch + 2 < NC) {
            ISSUE_GEMM_CHUNK(ch + 2, st);
            asm volatile("cp.async.wait_group 1;\n");
            __syncthreads();
        } else if (ch + 1 < NC) {
            asm volatile("cp.async.wait_group 0;\n");
            __syncthreads();
        }
    }

    #pragma unroll
    for (int mt = 0; mt < 2; mt++) {
        const int r = row0 + wm * 32 + mt * 16 + (lane >> 2);
        #pragma unroll
        for (int nt = 0; nt < 4; nt++) {
            const int cl = wn * 32 + nt * 8 + (lane & 3) * 2;
            const float b0 = bsm[cl], b1 = bsm[cl + 1];
            float2 v0 = {acc[mt][nt][0] + b0, acc[mt][nt][1] + b1};
            float2 v1 = {acc[mt][nt][2] + b0, acc[mt][nt][3] + b1};
            *(float2*)&C[r * DIM + col0 + cl]       = v0;
            *(float2*)&C[(r + 8) * DIM + col0 + cl] = v1;
        }
    }
}

// ---------------------------------------------------------------------------
// Attention kernel. Block = (batch b, QT=8 q's), 1024 threads = 32 warps.
// Warp w -> (q = w>>2, u-quarter = w&3). Score inner loop now evaluates tanh
// two-at-a-time with tanh.approx.f16x2 (halves MUFU pipe occupancy, the
// measured bottleneck); inputs computed in fp32, packed via cvt.rn.f16x2.f32,
// accumulation kept in fp32.
// ---------------------------------------------------------------------------
#define QT   8
#define EB   16                  // encoder rows per chunk
#define NCH  (S_ENC / EB)        // 16
#define ATH  1024
#define CHV  (EB * DIM / 4)      // 2048 float4 per chunk
#define PFT  (CHV / ATH)         // 2 float4 per thread

__device__ __forceinline__ uint32_t tanh2(uint32_t x) {
    asm("tanh.approx.f16x2 %0, %0;" : "+r"(x));
    return x;
}

__global__ __launch_bounds__(ATH, 1) void attn_kernel(
    const float* __restrict__ enc,      // [B, S_ENC, DIM] raw encodings
    const float* __restrict__ wscore,   // [DIM]
    const float* __restrict__ bscore,   // [1]
    float* __restrict__ out)            // [B, S_DEC, DIM]
{
    extern __shared__ float smem[];
    float* s_de   = smem;                         // 2*EB*DIM   (16384 f)
    float* s_part = s_de + 2 * EB * DIM;          // 32*S_ENC   (8192 f)
    float* s_sc   = s_part + 32 * S_ENC;          // QT*S_ENC   (2048 f)
    float* s_t    = s_sc + QT * S_ENC;            // S_ENC*QT   (2048 f)

    const int b    = blockIdx.y;
    const int q0   = blockIdx.x * QT;
    const int tid  = threadIdx.x;
    const int lane = tid & 31;
    const int w    = tid >> 5;
    const int q    = w >> 2;            // local q in [0,8)
    const int quad = w & 3;             // u-quarter
    const int u0   = quad * 128 + lane;

    // ---- loop-invariant registers -----------------------------------------
    float ddr[4], wsr[4];
    {
        const float* ddp = g_ddec + (b * S_DEC + q0 + q) * DIM;
        #pragma unroll
        for (int i = 0; i < 4; i++) {
            ddr[i] = ddp[u0 + 32 * i];
            wsr[i] = wscore[u0 + 32 * i];
        }
    }

    const float4* gsrc = (const float4*)(g_denc + b * S_ENC * DIM);
    const unsigned sde_base = (unsigned)__cvta_generic_to_shared(s_de);

    #define ISSUE_CHUNK(ch, buf)                                               \
        do {                                                                   \
            _Pragma("unroll")                                                  \
            for (int j = 0; j < PFT; j++) {                                    \
                const int idx = j * ATH + tid;                                 \
                const unsigned dst = sde_base + ((buf) * CHV + idx) * 16u;     \
                const float4* srcp = gsrc + (ch) * CHV + idx;                  \
                asm volatile("cp.async.cg.shared.global [%0], [%1], 16;\n"     \
                             :: "r"(dst), "l"(srcp));                          \
            }                                                                  \
            asm volatile("cp.async.commit_group;\n");                          \
        } while (0)

    ISSUE_CHUNK(0, 0);
    ISSUE_CHUNK(1, 1);
    asm volatile("cp.async.wait_group 1;\n");
    __syncthreads();

    // ---- score chunks ------------------------------------------------------
    for (int ch = 0; ch < NCH; ch++) {
        const float* de = s_de + (ch & 1) * EB * DIM + u0;

        float acc[EB];
        #pragma unroll
        for (int e = 0; e < EB; e++) {
            const float* dep = de + e * DIM;
            const float x0 = ddr[0] + dep[0];
            const float x1 = ddr[1] + dep[32];
            const float x2 = ddr[2] + dep[64];
            const float x3 = ddr[3] + dep[96];
            __half2 h01 = __floats2half2_rn(x0, x1);
            __half2 h23 = __floats2half2_rn(x2, x3);
            const uint32_t t01u = tanh2(*reinterpret_cast<uint32_t*>(&h01));
            const uint32_t t23u = tanh2(*reinterpret_cast<uint32_t*>(&h23));
            const __half2 t01 = *reinterpret_cast<const __half2*>(&t01u);
            const __half2 t23 = *reinterpret_cast<const __half2*>(&t23u);
            float s = __low2float(t01) * wsr[0];
            s = fmaf(__high2float(t01), wsr[1], s);
            s = fmaf(__low2float(t23),  wsr[2], s);
            s = fmaf(__high2float(t23), wsr[3], s);
            acc[e] = s;
        }

        // multi-value butterfly: fold 16 values over stages s=16..2, then s=1
        #pragma unroll
        for (int s = 16, n = 8; s >= 2; s >>= 1, n >>= 1) {
            const bool hi = (lane & s) != 0;
            #pragma unroll
            for (int j = 0; j < n; j++) {
                const float send = hi ? acc[j] : acc[j + n];
                const float keep = hi ? acc[j + n] : acc[j];
                acc[j] = keep + __shfl_xor_sync(0xFFFFFFFFu, send, s);
            }
        }
        acc[0] += __shfl_xor_sync(0xFFFFFFFFu, acc[0], 1);
        if ((lane & 1) == 0)
            s_part[w * S_ENC + ch * EB + ((lane >> 1) & 15)] = acc[0];

        if (ch + 1 < NCH) {
            __syncthreads();                       // done reading buf[ch&1]
            if (ch + 2 < NCH) {
                ISSUE_CHUNK(ch + 2, (ch & 1));
                asm volatile("cp.async.wait_group 1;\n");
            } else {
                asm volatile("cp.async.wait_group 0;\n");
            }
            __syncthreads();                       // new buffer visible
        }
    }
    __syncthreads();   // all s_part written

    // ---- combine quarter-sums + bias --------------------------------------
    const float bsc = bscore[0];
    for (int idx = tid; idx < QT * S_ENC; idx += ATH) {
        const int qq = idx >> 8, e = idx & (S_ENC - 1);
        s_sc[qq * S_ENC + e] =
            s_part[(4 * qq + 0) * S_ENC + e] + s_part[(4 * qq + 1) * S_ENC + e] +
            s_part[(4 * qq + 2) * S_ENC + e] + s_part[(4 * qq + 3) * S_ENC + e] + bsc;
    }
    __syncthreads();

    // ---- softmax (warps 0-7 handle q=w); write transposed [e][q] ----------
    if (w < QT) {
        float v[S_ENC / 32];
        float m = -1e30f;
        #pragma unroll
        for (int i = 0; i < S_ENC / 32; i++) {
            v[i] = s_sc[w * S_ENC + lane + 32 * i];
            m = fmaxf(m, v[i]);
        }
        #pragma unroll
        for (int off = 16; off; off >>= 1)
            m = fmaxf(m, __shfl_xor_sync(0xFFFFFFFFu, m, off));
        float sum = 0.f;
        #pragma unroll
        for (int i = 0; i < S_ENC / 32; i++) {
            v[i] = __expf(v[i] - m);
            sum += v[i];
        }
        #pragma unroll
        for (int off = 16; off; off >>= 1)
            sum += __shfl_xor_sync(0xFFFFFFFFu, sum, off);
        const float inv = 1.f / sum;
        #pragma unroll
        for (int i = 0; i < S_ENC / 32; i++)
            s_t[(lane + 32 * i) * QT + w] = v[i] * inv;
    }
    __syncthreads();

    // ---- context: warp w owns dims [w*16, w*16+16); half-warps split e ----
    const int dl = lane & 15;
    const int eh = lane >> 4;           // 0/1 -> e-half
    const int d0 = w * 16 + dl;
    float c[QT] = {};
    const float* ep = enc + b * S_ENC * DIM;

    const int e_beg = eh * 128;
    #pragma unroll 4
    for (int e = e_beg; e < e_beg + 128; e++) {
        const float ev = ep[e * DIM + d0];
        const float4 w0 = *(const float4*)&s_t[e * QT];       // broadcast
        const float4 w1 = *(const float4*)&s_t[e * QT + 4];
        c[0] = fmaf(w0.x, ev, c[0]);
        c[1] = fmaf(w0.y, ev, c[1]);
        c[2] = fmaf(w0.z, ev, c[2]);
        c[3] = fmaf(w0.w, ev, c[3]);
        c[4] = fmaf(w1.x, ev, c[4]);
        c[5] = fmaf(w1.y, ev, c[5]);
        c[6] = fmaf(w1.z, ev, c[6]);
        c[7] = fmaf(w1.w, ev, c[7]);
    }
    #pragma unroll
    for (int qq = 0; qq < QT; qq++)
        c[qq] += __shfl_xor_sync(0xFFFFFFFFu, c[qq], 16);

    if (lane < 16) {
        #pragma unroll
        for (int qq = 0; qq < QT; qq++)
            out[(b * S_DEC + q0 + qq) * DIM + d0] = c[qq];
    }
}

#define ATTN_SMEM ((2 * EB * DIM + 32 * S_ENC + 2 * QT * S_ENC) * (int)sizeof(float))

// ---------------------------------------------------------------------------
extern "C" void kernel_launch(void* const* d_in, const int* in_sizes, int n_in,
                              void* d_out, int out_size)
{
    const float* encodings = (const float*)d_in[0];   // [8,256,512]
    const float* decodings = (const float*)d_in[1];   // [8,128,512]
    const float* W_enc     = (const float*)d_in[2];   // [512,512]
    const float* W_dec     = (const float*)d_in[3];   // [512,512]
    const float* W_score   = (const float*)d_in[4];   // [512,1]
    const float* bias_enc  = (const float*)d_in[5];   // [512]
    const float* bias_dec  = (const float*)d_in[6];   // [512]
    const float* bias_sc   = (const float*)d_in[7];   // [1]
    float* out = (float*)d_out;                       // [8,128,512]

    void* p_denc = nullptr;
    void* p_ddec = nullptr;
    cudaGetSymbolAddress(&p_denc, g_denc);
    cudaGetSymbolAddress(&p_ddec, g_ddec);

    cudaFuncSetAttribute(attn_kernel,
                         cudaFuncAttributeMaxDynamicSharedMemorySize, ATTN_SMEM);

    // both projections in one tensor-core launch (z selects enc/dec)
    {
        dim3 grid(DIM / TBN, (NB * S_ENC) / TBM, 2);   // (8, 32, 2)
        gemm_tf32_kernel<<<grid, 128>>>(encodings, W_enc, bias_enc, (float*)p_denc,
                                        decodings, W_dec, bias_dec, (float*)p_ddec);
    }

    // scores + softmax + context
    {
        dim3 grid(S_DEC / QT, NB);                     // (16, 8)
        attn_kernel<<<grid, ATH, ATTN_SMEM>>>(encodings, W_score, bias_sc, out);
    }
}